// round 9
// baseline (speedup 1.0000x reference)
#include <cuda_runtime.h>
#include <cuda_bf16.h>
#include <cstdint>

#define TN   32768
#define D    128
#define BG   64
#define NG   512
#define ET   524288
#define NH   4
#define CAP  96

typedef unsigned long long u64;

// ---------------- scratch ----------------
__device__ float g_h  [TN * D];
__device__ float g_h2 [TN * D];
__device__ float g_q  [TN * D];
__device__ float g_kv [TN * 256];
__device__ float g_ao [TN * D];
__device__ float g_wt [640 * 128];   // wt0@0 (gcn), wt1@16384 (q), wt2@32768 (kv), wt3@65536 (out)
__device__ float g_deg[TN];
__device__ int   g_cnt[TN];
__device__ u64   g_bkt[TN * CAP];

// ---------------- f32x2 helpers ----------------
#define FMA2(d,a,b) asm("fma.rn.f32x2 %0, %1, %2, %0;" : "+l"(d) : "l"(a), "l"(b))
#define MUL2(d,a)   asm("mul.rn.f32x2 %0, %0, %1;"     : "+l"(d) : "l"(a))

__device__ __forceinline__ u64 pk2(float lo, float hi) {
    u64 r;
    asm("mov.b64 %0, {%1, %2};" : "=l"(r)
        : "r"(__float_as_uint(lo)), "r"(__float_as_uint(hi)));
    return r;
}
__device__ __forceinline__ float hadd2(u64 v) {
    unsigned int lo, hi;
    asm("mov.b64 {%0, %1}, %2;" : "=r"(lo), "=r"(hi) : "l"(v));
    return __uint_as_float(lo) + __uint_as_float(hi);
}

// ---------------- K0: fused init + weight transposes ----------------
__global__ void init_wtrans_kernel(const float* __restrict__ Wg,
                                   const float* __restrict__ Wq,
                                   const float* __restrict__ Wkv,
                                   const float* __restrict__ Wo) {
    __shared__ float t[32][33];
    int bid = blockIdx.x;
    if (bid < 128) {
        int i = bid * 256 + threadIdx.y * 32 + threadIdx.x;
        g_deg[i] = 1.0f;
        g_cnt[i] = 0;
        return;
    }
    int w = bid - 128;            // 0..127
    int z  = w >> 5;
    int by = (w >> 3) & 3;
    int bx = w & 7;
    const float* W; float* WT; int ncols;
    if (z == 0)      { W = Wg;  WT = g_wt;          ncols = 128; }
    else if (z == 1) { W = Wq;  WT = g_wt + 16384;  ncols = 128; }
    else if (z == 2) { W = Wkv; WT = g_wt + 32768;  ncols = 256; }
    else             { W = Wo;  WT = g_wt + 65536;  ncols = 128; }
    if (bx * 32 >= ncols) return;
    int c = bx * 32 + threadIdx.x;
    int k = by * 32 + threadIdx.y;
#pragma unroll
    for (int i = 0; i < 32; i += 8)
        t[threadIdx.y + i][threadIdx.x] = W[(k + i) * ncols + c];
    __syncthreads();
    int c2 = bx * 32 + threadIdx.y;
    int k2 = by * 32 + threadIdx.x;
#pragma unroll
    for (int i = 0; i < 32; i += 8)
        WT[(c2 + i) * 128 + k2] = t[threadIdx.x][threadIdx.y + i];
}

// ---------------- GEMM body (f32x2, 128x64 tile, conflict-free smem geometry) ----------------
// As: 128 rows x 132-float stride (16B aligned; warp rg-pairs land on disjoint banks)
// Ws: 64 cols  x 130-float stride ([c][k] u64 pairs; cols read at spacing 16 -> distinct banks)
// thread tile: rows rg+16*ri (ri<8), cols cg+16*j (j<4)
#define AS_STRIDE 132
#define GEMM_SMEM_FLOATS (128 * AS_STRIDE + 64 * 130)

__device__ __forceinline__ void gemm_body(const float* __restrict__ A,
                                          long long m0,
                                          const float* __restrict__ WTpart,
                                          const float* __restrict__ biasPart,
                                          float* __restrict__ out,
                                          int out_ld, int out_col0,
                                          float* sm) {
    float* As  = sm;
    float* WsT = sm + 128 * AS_STRIDE;
    int tid = threadIdx.x;

    const float4* A4 = (const float4*)(A + m0 * 128);
#pragma unroll
    for (int i = 0; i < 16; i++) {
        int idx = tid + i * 256;
        int r  = idx >> 5;
        int c4 = idx & 31;
        *(float4*)(As + r * AS_STRIDE + c4 * 4) = A4[idx];
    }

    const float4* WT4 = (const float4*)WTpart;
#pragma unroll
    for (int i = 0; i < 8; i++) {
        int idx = tid + i * 256;
        int c  = idx >> 5;
        int k4 = idx & 31;
        float4 w = WT4[idx];
        u64* dst = (u64*)(WsT + c * 130 + k4 * 4);
        dst[0] = ((const u64*)&w)[0];
        dst[1] = ((const u64*)&w)[1];
    }
    __syncthreads();

    int cg = tid & 15;
    int rg = tid >> 4;

    u64 acc[8][4];
#pragma unroll
    for (int i = 0; i < 8; i++)
#pragma unroll
        for (int j = 0; j < 4; j++) acc[i][j] = 0ull;

    const u64* Wu = (const u64*)WsT;   // per-col stride 65 u64

#pragma unroll 2
    for (int kk2 = 0; kk2 < 32; kk2++) {
        u64 w0[4], w1[4];
#pragma unroll
        for (int j = 0; j < 4; j++) {
            const u64* wp = Wu + (cg + 16 * j) * 65 + 2 * kk2;
            w0[j] = wp[0];
            w1[j] = wp[1];
        }
#pragma unroll
        for (int ri = 0; ri < 8; ri++) {
            ulonglong2 a2 = *(const ulonglong2*)(As + (rg + 16 * ri) * AS_STRIDE + kk2 * 4);
#pragma unroll
            for (int j = 0; j < 4; j++) {
                FMA2(acc[ri][j], a2.x, w0[j]);
                FMA2(acc[ri][j], a2.y, w1[j]);
            }
        }
    }

    float bb[4] = {0.f, 0.f, 0.f, 0.f};
    if (biasPart) {
#pragma unroll
        for (int j = 0; j < 4; j++) bb[j] = biasPart[cg + 16 * j];
    }
#pragma unroll
    for (int ri = 0; ri < 8; ri++) {
        long long row = m0 + rg + 16 * ri;
#pragma unroll
        for (int j = 0; j < 4; j++)
            out[row * out_ld + out_col0 + cg + 16 * j] = hadd2(acc[ri][j]) + bb[j];
    }
}

// ---------------- K1: fused scatter + GCN GEMM (interleaved 1:4) ----------------
__global__ void __launch_bounds__(256, 2)
scatter_gcn_kernel(const int* __restrict__ ei, const float* __restrict__ x,
                   const float* __restrict__ bg) {
    extern __shared__ float sm[];
    int bid = blockIdx.x;
    if (bid % 5 == 0) {
        int gid = bid / 5;               // 0..511
        int bx = gid & 255, by = gid >> 8;
        int cb = by * 64;
        gemm_body(x, (long long)bx * 128, g_wt + cb * 128, bg + cb,
                  g_h, 128, cb, sm);
    } else {
        int sid = bid - (bid / 5 + 1);   // 0..2047
        int e = sid * 256 + threadIdx.x;
        int r = ei[e];
        int c = ei[ET + e];
        atomicAdd(&g_deg[r], 1.0f);
        int pos = atomicAdd(&g_cnt[c], 1);
        if (pos < CAP)
            g_bkt[(long long)c * CAP + pos] = (u64)(unsigned)e | ((u64)(unsigned)r << 32);
    }
}

// standard GEMM: (TN x 128) @ (128 x ncols)
__global__ void __launch_bounds__(256, 2)
gemm_kernel(const float* __restrict__ A, const float* __restrict__ WT,
            int ncols, const float* __restrict__ bias, float* __restrict__ out) {
    extern __shared__ float sm[];
    int cb = blockIdx.y * 64;
    gemm_body(A, (long long)blockIdx.x * 128, WT + cb * 128,
              bias ? bias + cb : nullptr, out, ncols, cb, sm);
}

// fused q + kv projections: grid.y in [0,6)
__global__ void __launch_bounds__(256, 2)
qkv_gemm_kernel(const float* __restrict__ A) {
    extern __shared__ float sm[];
    int y = blockIdx.y;
    if (y < 2) {
        int cb = y * 64;
        gemm_body(A, (long long)blockIdx.x * 128, g_wt + 16384 + cb * 128,
                  nullptr, g_q, 128, cb, sm);
    } else {
        int cb = (y - 2) * 64;
        gemm_body(A, (long long)blockIdx.x * 128, g_wt + 32768 + cb * 128,
                  nullptr, g_kv, 256, cb, sm);
    }
}

// ---------------- K2: gather (warp-batched, MLP-unrolled) ----------------
__global__ void gather_kernel(const float* __restrict__ ee,
                              const float* __restrict__ root) {
    int gw = (blockIdx.x * blockDim.x + threadIdx.x) >> 5;
    int lane = threadIdx.x & 31;
    if (gw >= TN) return;
    int n = gw;
    float degn = g_deg[n];
    float dc = rsqrtf(degn);
    int cnt = g_cnt[n]; if (cnt > CAP) cnt = CAP;
    const float4* h4 = (const float4*)g_h;
    const float4* e4 = (const float4*)ee;
    const u64* bkt = g_bkt + (long long)n * CAP;
    float4 acc = make_float4(0.f, 0.f, 0.f, 0.f);

    for (int base = 0; base < cnt; base += 32) {
        int m = min(32, cnt - base);
        u64 pr = 0;
        if (lane < m) pr = bkt[base + lane];
        int r_l = (int)(unsigned)(pr >> 32);
        int e_l = (int)(unsigned)pr;
        float nm_l = 0.f;
        if (lane < m) nm_l = dc * rsqrtf(g_deg[r_l]);

        int p = 0;
        for (; p + 4 <= m; p += 4) {
            float4 hv[4], ev[4];
            float nm[4];
#pragma unroll
            for (int j = 0; j < 4; j++) {
                int r   = __shfl_sync(0xffffffffu, r_l, p + j);
                int eid = __shfl_sync(0xffffffffu, e_l, p + j);
                nm[j]   = __shfl_sync(0xffffffffu, nm_l, p + j);
                hv[j] = h4[r * 32 + lane];
                ev[j] = __ldcs(e4 + (long long)eid * 32 + lane);
            }
#pragma unroll
            for (int j = 0; j < 4; j++) {
                acc.x += nm[j] * fmaxf(hv[j].x + ev[j].x, 0.f);
                acc.y += nm[j] * fmaxf(hv[j].y + ev[j].y, 0.f);
                acc.z += nm[j] * fmaxf(hv[j].z + ev[j].z, 0.f);
                acc.w += nm[j] * fmaxf(hv[j].w + ev[j].w, 0.f);
            }
        }
        for (; p < m; p++) {
            int r   = __shfl_sync(0xffffffffu, r_l, p);
            int eid = __shfl_sync(0xffffffffu, e_l, p);
            float nm = __shfl_sync(0xffffffffu, nm_l, p);
            float4 hv = h4[r * 32 + lane];
            float4 ev = __ldcs(e4 + (long long)eid * 32 + lane);
            acc.x += nm * fmaxf(hv.x + ev.x, 0.f);
            acc.y += nm * fmaxf(hv.y + ev.y, 0.f);
            acc.z += nm * fmaxf(hv.z + ev.z, 0.f);
            acc.w += nm * fmaxf(hv.w + ev.w, 0.f);
        }
    }

    float4 hs = h4[n * 32 + lane];
    float4 rt = ((const float4*)root)[lane];
    float inv = 1.0f / degn;
    acc.x += fmaxf(hs.x + rt.x, 0.f) * inv;
    acc.y += fmaxf(hs.y + rt.y, 0.f) * inv;
    acc.z += fmaxf(hs.z + rt.z, 0.f) * inv;
    acc.w += fmaxf(hs.w + rt.w, 0.f) * inv;
    ((float4*)g_h2)[n * 32 + lane] = acc;
}

// ---------------- attention (frozen R2/R4 version) ----------------
__global__ void __launch_bounds__(256) attn_kernel() {
    extern __shared__ float sm[];
    float4* Ks4 = (float4*)sm;          // 512*8 float4 = 64KB
    float4* Vs4 = Ks4 + 512 * 8;        // 64KB
    int tid = threadIdx.x;
    int b = blockIdx.x >> 2;
    int h = blockIdx.x & 3;
    int nbase = b * NG;

    const float4* KV4 = (const float4*)g_kv;
    for (int idx = tid; idx < NG * 8; idx += 256) {
        int j  = idx >> 3;
        int d4 = idx & 7;
        Ks4[idx] = KV4[(nbase + j) * 64 + h * 8 + d4];
        Vs4[idx] = KV4[(nbase + j) * 64 + 32 + h * 8 + d4];
    }
    __syncthreads();

    const float scale = 0.17677669529663687f;
    u64 q0[16], q1[16];
    const float4* Q4 = (const float4*)g_q;
#pragma unroll
    for (int d4 = 0; d4 < 8; d4++) {
        float4 a = Q4[(nbase + tid) * 32 + h * 8 + d4];
        q0[2 * d4]     = pk2(a.x * scale, a.y * scale);
        q0[2 * d4 + 1] = pk2(a.z * scale, a.w * scale);
        float4 c = Q4[(nbase + tid + 256) * 32 + h * 8 + d4];
        q1[2 * d4]     = pk2(c.x * scale, c.y * scale);
        q1[2 * d4 + 1] = pk2(c.z * scale, c.w * scale);
    }

    u64 o0[16], o1[16];
#pragma unroll
    for (int d = 0; d < 16; d++) { o0[d] = 0ull; o1[d] = 0ull; }
    float m0 = -1e30f, l0 = 0.f, m1 = -1e30f, l1 = 0.f;

    for (int jt = 0; jt < NG; jt += 8) {
        float s0[8], s1[8];
#pragma unroll
        for (int jj = 0; jj < 8; jj++) {
            const ulonglong2* kp = (const ulonglong2*)(Ks4 + (jt + jj) * 8);
            u64 a0 = 0ull, b0 = 0ull, a1 = 0ull, b1 = 0ull;
#pragma unroll
            for (int d = 0; d < 8; d++) {
                ulonglong2 kk = kp[d];
                FMA2(a0, q0[2 * d], kk.x);
                FMA2(b0, q0[2 * d + 1], kk.y);
                FMA2(a1, q1[2 * d], kk.x);
                FMA2(b1, q1[2 * d + 1], kk.y);
            }
            s0[jj] = hadd2(a0) + hadd2(b0);
            s1[jj] = hadd2(a1) + hadd2(b1);
        }
        float tm0 = s0[0], tm1 = s1[0];
#pragma unroll
        for (int jj = 1; jj < 8; jj++) { tm0 = fmaxf(tm0, s0[jj]); tm1 = fmaxf(tm1, s1[jj]); }
        float nm0 = fmaxf(m0, tm0), nm1 = fmaxf(m1, tm1);
        float al0 = __expf(m0 - nm0), al1 = __expf(m1 - nm1);
        m0 = nm0; m1 = nm1;
        l0 *= al0; l1 *= al1;
        u64 al0p = pk2(al0, al0), al1p = pk2(al1, al1);
#pragma unroll
        for (int d = 0; d < 16; d++) { MUL2(o0[d], al0p); MUL2(o1[d], al1p); }
#pragma unroll
        for (int jj = 0; jj < 8; jj++) {
            float p0 = __expf(s0[jj] - m0); l0 += p0;
            float p1 = __expf(s1[jj] - m1); l1 += p1;
            u64 p0p = pk2(p0, p0), p1p = pk2(p1, p1);
            const ulonglong2* vp = (const ulonglong2*)(Vs4 + (jt + jj) * 8);
#pragma unroll
            for (int d = 0; d < 8; d++) {
                ulonglong2 vv = vp[d];
                FMA2(o0[2 * d],     p0p, vv.x);
                FMA2(o0[2 * d + 1], p0p, vv.y);
                FMA2(o1[2 * d],     p1p, vv.x);
                FMA2(o1[2 * d + 1], p1p, vv.y);
            }
        }
    }

    float inv0 = 1.0f / l0, inv1 = 1.0f / l1;
    u64 i0p = pk2(inv0, inv0), i1p = pk2(inv1, inv1);
    ulonglong2* O = (ulonglong2*)g_ao;
#pragma unroll
    for (int d = 0; d < 8; d++) {
        MUL2(o0[2 * d], i0p); MUL2(o0[2 * d + 1], i0p);
        MUL2(o1[2 * d], i1p); MUL2(o1[2 * d + 1], i1p);
        O[(nbase + tid) * 32 + h * 8 + d]       = make_ulonglong2(o0[2 * d], o0[2 * d + 1]);
        O[(nbase + tid + 256) * 32 + h * 8 + d] = make_ulonglong2(o1[2 * d], o1[2 * d + 1]);
    }
}

// ---------------- launch ----------------
extern "C" void kernel_launch(void* const* d_in, const int* in_sizes, int n_in,
                              void* d_out, int out_size) {
    const float* x    = (const float*)d_in[0];
    const int*   ei   = (const int*)d_in[1];
    const float* ee   = (const float*)d_in[2];
    const float* Wg   = (const float*)d_in[4];
    const float* bg   = (const float*)d_in[5];
    const float* root = (const float*)d_in[6];
    const float* Wq   = (const float*)d_in[7];
    const float* Wkv  = (const float*)d_in[8];
    const float* Wo   = (const float*)d_in[9];
    const float* bo   = (const float*)d_in[10];
    float* outp = (float*)d_out;

    float *p_h2, *p_ao, *p_wt;
    cudaGetSymbolAddress((void**)&p_h2, g_h2);
    cudaGetSymbolAddress((void**)&p_ao, g_ao);
    cudaGetSymbolAddress((void**)&p_wt, g_wt);

    const int GEMM_SMEM = GEMM_SMEM_FLOATS * 4;   // 100864 B
    const int ATTN_SMEM = 128 * 1024;
    cudaFuncSetAttribute(scatter_gcn_kernel, cudaFuncAttributeMaxDynamicSharedMemorySize, GEMM_SMEM);
    cudaFuncSetAttribute(gemm_kernel,        cudaFuncAttributeMaxDynamicSharedMemorySize, GEMM_SMEM);
    cudaFuncSetAttribute(qkv_gemm_kernel,    cudaFuncAttributeMaxDynamicSharedMemorySize, GEMM_SMEM);
    cudaFuncSetAttribute(attn_kernel,        cudaFuncAttributeMaxDynamicSharedMemorySize, ATTN_SMEM);

    // 0: init + all weight transposes (fused)
    init_wtrans_kernel<<<256, dim3(32, 8)>>>(Wg, Wq, Wkv, Wo);
    // 1: fused scatter + GCN GEMM
    scatter_gcn_kernel<<<2560, 256, GEMM_SMEM>>>(ei, x, bg);
    // 2: gather -> h2
    gather_kernel<<<TN / 8, 256>>>(ee, root);
    // 3: fused q + kv projections  (PROFILED SLOT)
    qkv_gemm_kernel<<<dim3(TN / 128, 6), 256, GEMM_SMEM>>>(p_h2);
    // 4: attention
    attn_kernel<<<BG * NH, 256, ATTN_SMEM>>>();
    // 5: out = ao @ Wout + b_out
    gemm_kernel<<<dim3(TN / 128, 2), 256, GEMM_SMEM>>>(p_ao, p_wt + 65536, 128, bo, outp);
}

// round 10
// speedup vs baseline: 1.0119x; 1.0119x over previous
#include <cuda_runtime.h>
#include <cuda_bf16.h>
#include <cstdint>

#define TN   32768
#define D    128
#define BG   64
#define NG   512
#define ET   524288
#define NH   4
#define CAP  96

typedef unsigned long long u64;

// ---------------- scratch ----------------
__device__ float g_h  [TN * D];
__device__ float g_h2 [TN * D];
__device__ float g_q  [TN * D];
__device__ float g_kv [TN * 256];
__device__ float g_ao [TN * D];
__device__ float g_wt [640 * 128];   // wt1@16384 (q), wt2@32768 (kv), wt3@65536 (out)
__device__ int   g_odeg[TN];         // out-degree (zero-init; re-zeroed by last kernel)
__device__ int   g_cnt[TN];          // in-degree  (zero-init; re-zeroed by last kernel)
__device__ u64   g_bkt[TN * CAP];

// ---------------- f32x2 helpers ----------------
#define FMA2(d,a,b) asm("fma.rn.f32x2 %0, %1, %2, %0;" : "+l"(d) : "l"(a), "l"(b))
#define MUL2(d,a)   asm("mul.rn.f32x2 %0, %0, %1;"     : "+l"(d) : "l"(a))

__device__ __forceinline__ u64 pk2(float lo, float hi) {
    u64 r;
    asm("mov.b64 %0, {%1, %2};" : "=l"(r)
        : "r"(__float_as_uint(lo)), "r"(__float_as_uint(hi)));
    return r;
}
__device__ __forceinline__ float hadd2(u64 v) {
    unsigned int lo, hi;
    asm("mov.b64 {%0, %1}, %2;" : "=r"(lo), "=r"(hi) : "l"(v));
    return __uint_as_float(lo) + __uint_as_float(hi);
}

// ---------------- GEMM geometry ----------------
#define AS_STRIDE 132
#define GEMM_SMEM_FLOATS (128 * AS_STRIDE + 64 * 130)

// math core after smem tiles are loaded (rows rg+16*ri, cols cg+16*j)
__device__ __forceinline__ void gemm_math(long long m0,
                                          const float* __restrict__ biasPart,
                                          float* __restrict__ out,
                                          int out_ld, int out_col0,
                                          float* As, float* WsT) {
    int tid = threadIdx.x;
    int cg = tid & 15;
    int rg = tid >> 4;

    u64 acc[8][4];
#pragma unroll
    for (int i = 0; i < 8; i++)
#pragma unroll
        for (int j = 0; j < 4; j++) acc[i][j] = 0ull;

    const u64* Wu = (const u64*)WsT;   // per-col stride 65 u64

#pragma unroll 2
    for (int kk2 = 0; kk2 < 32; kk2++) {
        u64 w0[4], w1[4];
#pragma unroll
        for (int j = 0; j < 4; j++) {
            const u64* wp = Wu + (cg + 16 * j) * 65 + 2 * kk2;
            w0[j] = wp[0];
            w1[j] = wp[1];
        }
#pragma unroll
        for (int ri = 0; ri < 8; ri++) {
            ulonglong2 a2 = *(const ulonglong2*)(As + (rg + 16 * ri) * AS_STRIDE + kk2 * 4);
#pragma unroll
            for (int j = 0; j < 4; j++) {
                FMA2(acc[ri][j], a2.x, w0[j]);
                FMA2(acc[ri][j], a2.y, w1[j]);
            }
        }
    }

    float bb[4] = {0.f, 0.f, 0.f, 0.f};
    if (biasPart) {
#pragma unroll
        for (int j = 0; j < 4; j++) bb[j] = biasPart[cg + 16 * j];
    }
#pragma unroll
    for (int ri = 0; ri < 8; ri++) {
        long long row = m0 + rg + 16 * ri;
#pragma unroll
        for (int j = 0; j < 4; j++)
            out[row * out_ld + out_col0 + cg + 16 * j] = hadd2(acc[ri][j]) + bb[j];
    }
}

__device__ __forceinline__ void load_A_tile(const float* __restrict__ A, long long m0, float* As) {
    int tid = threadIdx.x;
    const float4* A4 = (const float4*)(A + m0 * 128);
#pragma unroll
    for (int i = 0; i < 16; i++) {
        int idx = tid + i * 256;
        int r  = idx >> 5;
        int c4 = idx & 31;
        *(float4*)(As + r * AS_STRIDE + c4 * 4) = A4[idx];
    }
}

// W tile from pre-transposed g_wt (proven path)
__device__ __forceinline__ void load_W_pret(const float* __restrict__ WTpart, float* WsT) {
    int tid = threadIdx.x;
    const float4* WT4 = (const float4*)WTpart;
#pragma unroll
    for (int i = 0; i < 8; i++) {
        int idx = tid + i * 256;
        int c  = idx >> 5;
        int k4 = idx & 31;
        float4 w = WT4[idx];
        u64* dst = (u64*)(WsT + c * 130 + k4 * 4);
        dst[0] = ((const u64*)&w)[0];
        dst[1] = ((const u64*)&w)[1];
    }
}

// W tile transposed on the fly from row-major W[k][ncols] (cols cb..cb+63)
__device__ __forceinline__ void load_W_direct(const float* __restrict__ W, int ncols, int cb, float* WsT) {
    int tid = threadIdx.x;
#pragma unroll
    for (int i = 0; i < 8; i++) {
        int idx = tid + i * 256;      // 0..2047
        int c  = idx & 63;
        int k4 = idx >> 6;            // 0..31
#pragma unroll
        for (int j = 0; j < 4; j++)
            WsT[c * 130 + 4 * k4 + j] = W[(4 * k4 + j) * ncols + cb + c];
    }
}

// ---------------- K0: scatter + GCN GEMM (direct W) + wtrans(q,kv,out) ----------------
// blocks: [0,64) wtrans; then rel=bid-64: rel%5==0 -> gcn gemm (512), else scatter (2048)
__global__ void __launch_bounds__(256, 2)
scatter_gcn_kernel(const int* __restrict__ ei, const float* __restrict__ x,
                   const float* __restrict__ Wg, const float* __restrict__ bg,
                   const float* __restrict__ Wq, const float* __restrict__ Wkv,
                   const float* __restrict__ Wo) {
    extern __shared__ float sm[];
    int bid = blockIdx.x;
    if (bid < 64) {
        // transpose q/kv/out weights into g_wt
        __shared__ float t[32][33];
        int z, local;
        if (bid < 16)      { z = 1; local = bid; }
        else if (bid < 48) { z = 2; local = bid - 16; }
        else               { z = 3; local = bid - 48; }
        const float* W; float* WT; int ncols;
        if (z == 1)      { W = Wq;  WT = g_wt + 16384; ncols = 128; }
        else if (z == 2) { W = Wkv; WT = g_wt + 32768; ncols = 256; }
        else             { W = Wo;  WT = g_wt + 65536; ncols = 128; }
        int nbx = ncols >> 5;
        int bx = local % nbx;
        int by = local / nbx;
        int tx = threadIdx.x & 31, ty = threadIdx.x >> 5;
        int c = bx * 32 + tx;
        int k = by * 32 + ty;
#pragma unroll
        for (int i = 0; i < 32; i += 8)
            t[ty + i][tx] = W[(k + i) * ncols + c];
        __syncthreads();
        int c2 = bx * 32 + ty;
        int k2 = by * 32 + tx;
#pragma unroll
        for (int i = 0; i < 32; i += 8)
            WT[(c2 + i) * 128 + k2] = t[tx][ty + i];
        return;
    }
    int rel = bid - 64;
    if (rel % 5 == 0) {
        int gid = rel / 5;               // 0..511
        int bx = gid & 255, by = gid >> 8;
        int cb = by * 64;
        float* As  = sm;
        float* WsT = sm + 128 * AS_STRIDE;
        load_A_tile(x, (long long)bx * 128, As);
        load_W_direct(Wg, 128, cb, WsT);
        __syncthreads();
        gemm_math((long long)bx * 128, bg + cb, g_h, 128, cb, As, WsT);
    } else {
        int sid = rel - (rel / 5 + 1);   // 0..2047
        int e = sid * 256 + threadIdx.x;
        int r = ei[e];
        int c = ei[ET + e];
        atomicAdd(&g_odeg[r], 1);
        int pos = atomicAdd(&g_cnt[c], 1);
        if (pos < CAP)
            g_bkt[(long long)c * CAP + pos] = (u64)(unsigned)e | ((u64)(unsigned)r << 32);
    }
}

// ---------------- K1: gather (warp-batched, MLP-unrolled) ----------------
__global__ void gather_kernel(const float* __restrict__ ee,
                              const float* __restrict__ root) {
    int gw = (blockIdx.x * blockDim.x + threadIdx.x) >> 5;
    int lane = threadIdx.x & 31;
    if (gw >= TN) return;
    int n = gw;
    float degn = (float)g_odeg[n] + 1.0f;
    float dc = rsqrtf(degn);
    int cnt = g_cnt[n]; if (cnt > CAP) cnt = CAP;
    const float4* h4 = (const float4*)g_h;
    const float4* e4 = (const float4*)ee;
    const u64* bkt = g_bkt + (long long)n * CAP;
    float4 acc = make_float4(0.f, 0.f, 0.f, 0.f);

    for (int base = 0; base < cnt; base += 32) {
        int m = min(32, cnt - base);
        u64 pr = 0;
        if (lane < m) pr = bkt[base + lane];
        int r_l = (int)(unsigned)(pr >> 32);
        int e_l = (int)(unsigned)pr;
        float nm_l = 0.f;
        if (lane < m) nm_l = dc * rsqrtf((float)g_odeg[r_l] + 1.0f);

        int p = 0;
        for (; p + 4 <= m; p += 4) {
            float4 hv[4], ev[4];
            float nm[4];
#pragma unroll
            for (int j = 0; j < 4; j++) {
                int r   = __shfl_sync(0xffffffffu, r_l, p + j);
                int eid = __shfl_sync(0xffffffffu, e_l, p + j);
                nm[j]   = __shfl_sync(0xffffffffu, nm_l, p + j);
                hv[j] = h4[r * 32 + lane];
                ev[j] = __ldcs(e4 + (long long)eid * 32 + lane);
            }
#pragma unroll
            for (int j = 0; j < 4; j++) {
                acc.x += nm[j] * fmaxf(hv[j].x + ev[j].x, 0.f);
                acc.y += nm[j] * fmaxf(hv[j].y + ev[j].y, 0.f);
                acc.z += nm[j] * fmaxf(hv[j].z + ev[j].z, 0.f);
                acc.w += nm[j] * fmaxf(hv[j].w + ev[j].w, 0.f);
            }
        }
        for (; p < m; p++) {
            int r   = __shfl_sync(0xffffffffu, r_l, p);
            int eid = __shfl_sync(0xffffffffu, e_l, p);
            float nm = __shfl_sync(0xffffffffu, nm_l, p);
            float4 hv = h4[r * 32 + lane];
            float4 ev = __ldcs(e4 + (long long)eid * 32 + lane);
            acc.x += nm * fmaxf(hv.x + ev.x, 0.f);
            acc.y += nm * fmaxf(hv.y + ev.y, 0.f);
            acc.z += nm * fmaxf(hv.z + ev.z, 0.f);
            acc.w += nm * fmaxf(hv.w + ev.w, 0.f);
        }
    }

    float4 hs = h4[n * 32 + lane];
    float4 rt = ((const float4*)root)[lane];
    float inv = 1.0f / degn;
    acc.x += fmaxf(hs.x + rt.x, 0.f) * inv;
    acc.y += fmaxf(hs.y + rt.y, 0.f) * inv;
    acc.z += fmaxf(hs.z + rt.z, 0.f) * inv;
    acc.w += fmaxf(hs.w + rt.w, 0.f) * inv;
    ((float4*)g_h2)[n * 32 + lane] = acc;
}

// ---------------- K2: fused q + kv projections ----------------
__global__ void __launch_bounds__(256, 2)
qkv_gemm_kernel(const float* __restrict__ A) {
    extern __shared__ float sm[];
    float* As  = sm;
    float* WsT = sm + 128 * AS_STRIDE;
    int y = blockIdx.y;
    long long m0 = (long long)blockIdx.x * 128;
    load_A_tile(A, m0, As);
    if (y < 2) {
        int cb = y * 64;
        load_W_pret(g_wt + 16384 + cb * 128, WsT);
        __syncthreads();
        gemm_math(m0, nullptr, g_q, 128, cb, As, WsT);
    } else {
        int cb = (y - 2) * 64;
        load_W_pret(g_wt + 32768 + cb * 128, WsT);
        __syncthreads();
        gemm_math(m0, nullptr, g_kv, 256, cb, As, WsT);
    }
}

// ---------------- K3: attention (frozen) -- PROFILED SLOT ----------------
__global__ void __launch_bounds__(256) attn_kernel() {
    extern __shared__ float sm[];
    float4* Ks4 = (float4*)sm;          // 512*8 float4 = 64KB
    float4* Vs4 = Ks4 + 512 * 8;        // 64KB
    int tid = threadIdx.x;
    int b = blockIdx.x >> 2;
    int h = blockIdx.x & 3;
    int nbase = b * NG;

    const float4* KV4 = (const float4*)g_kv;
    for (int idx = tid; idx < NG * 8; idx += 256) {
        int j  = idx >> 3;
        int d4 = idx & 7;
        Ks4[idx] = KV4[(nbase + j) * 64 + h * 8 + d4];
        Vs4[idx] = KV4[(nbase + j) * 64 + 32 + h * 8 + d4];
    }
    __syncthreads();

    const float scale = 0.17677669529663687f;
    u64 q0[16], q1[16];
    const float4* Q4 = (const float4*)g_q;
#pragma unroll
    for (int d4 = 0; d4 < 8; d4++) {
        float4 a = Q4[(nbase + tid) * 32 + h * 8 + d4];
        q0[2 * d4]     = pk2(a.x * scale, a.y * scale);
        q0[2 * d4 + 1] = pk2(a.z * scale, a.w * scale);
        float4 c = Q4[(nbase + tid + 256) * 32 + h * 8 + d4];
        q1[2 * d4]     = pk2(c.x * scale, c.y * scale);
        q1[2 * d4 + 1] = pk2(c.z * scale, c.w * scale);
    }

    u64 o0[16], o1[16];
#pragma unroll
    for (int d = 0; d < 16; d++) { o0[d] = 0ull; o1[d] = 0ull; }
    float m0 = -1e30f, l0 = 0.f, m1 = -1e30f, l1 = 0.f;

    for (int jt = 0; jt < NG; jt += 8) {
        float s0[8], s1[8];
#pragma unroll
        for (int jj = 0; jj < 8; jj++) {
            const ulonglong2* kp = (const ulonglong2*)(Ks4 + (jt + jj) * 8);
            u64 a0 = 0ull, b0 = 0ull, a1 = 0ull, b1 = 0ull;
#pragma unroll
            for (int d = 0; d < 8; d++) {
                ulonglong2 kk = kp[d];
                FMA2(a0, q0[2 * d], kk.x);
                FMA2(b0, q0[2 * d + 1], kk.y);
                FMA2(a1, q1[2 * d], kk.x);
                FMA2(b1, q1[2 * d + 1], kk.y);
            }
            s0[jj] = hadd2(a0) + hadd2(b0);
            s1[jj] = hadd2(a1) + hadd2(b1);
        }
        float tm0 = s0[0], tm1 = s1[0];
#pragma unroll
        for (int jj = 1; jj < 8; jj++) { tm0 = fmaxf(tm0, s0[jj]); tm1 = fmaxf(tm1, s1[jj]); }
        float nm0 = fmaxf(m0, tm0), nm1 = fmaxf(m1, tm1);
        float al0 = __expf(m0 - nm0), al1 = __expf(m1 - nm1);
        m0 = nm0; m1 = nm1;
        l0 *= al0; l1 *= al1;
        u64 al0p = pk2(al0, al0), al1p = pk2(al1, al1);
#pragma unroll
        for (int d = 0; d < 16; d++) { MUL2(o0[d], al0p); MUL2(o1[d], al1p); }
#pragma unroll
        for (int jj = 0; jj < 8; jj++) {
            float p0 = __expf(s0[jj] - m0); l0 += p0;
            float p1 = __expf(s1[jj] - m1); l1 += p1;
            u64 p0p = pk2(p0, p0), p1p = pk2(p1, p1);
            const ulonglong2* vp = (const ulonglong2*)(Vs4 + (jt + jj) * 8);
#pragma unroll
            for (int d = 0; d < 8; d++) {
                ulonglong2 vv = vp[d];
                FMA2(o0[2 * d],     p0p, vv.x);
                FMA2(o0[2 * d + 1], p0p, vv.y);
                FMA2(o1[2 * d],     p1p, vv.x);
                FMA2(o1[2 * d + 1], p1p, vv.y);
            }
        }
    }

    float inv0 = 1.0f / l0, inv1 = 1.0f / l1;
    u64 i0p = pk2(inv0, inv0), i1p = pk2(inv1, inv1);
    ulonglong2* O = (ulonglong2*)g_ao;
#pragma unroll
    for (int d = 0; d < 8; d++) {
        MUL2(o0[2 * d], i0p); MUL2(o0[2 * d + 1], i0p);
        MUL2(o1[2 * d], i1p); MUL2(o1[2 * d + 1], i1p);
        O[(nbase + tid) * 32 + h * 8 + d]       = make_ulonglong2(o0[2 * d], o0[2 * d + 1]);
        O[(nbase + tid + 256) * 32 + h * 8 + d] = make_ulonglong2(o1[2 * d], o1[2 * d + 1]);
    }
}

// ---------------- K4: out GEMM + counter reset for next replay ----------------
__global__ void __launch_bounds__(256, 2)
out_gemm_kernel(const float* __restrict__ A, const float* __restrict__ bias,
                float* __restrict__ out) {
    extern __shared__ float sm[];
    if (blockIdx.x >= 256) {
        if (blockIdx.y != 0) return;
        // zero g_cnt + g_odeg (32 blocks x 256 threads x 8 ints = 65536 ints)
        int t = (blockIdx.x - 256) * 256 + threadIdx.x;   // 0..8191
        int4 z = make_int4(0, 0, 0, 0);
        ((int4*)g_cnt)[t]  = z;
        ((int4*)g_odeg)[t] = z;
        return;
    }
    float* As  = sm;
    float* WsT = sm + 128 * AS_STRIDE;
    int cb = blockIdx.y * 64;
    long long m0 = (long long)blockIdx.x * 128;
    load_A_tile(A, m0, As);
    load_W_pret(g_wt + 65536 + cb * 128, WsT);
    __syncthreads();
    gemm_math(m0, bias + cb, out, 128, cb, As, WsT);
}

// ---------------- launch ----------------
extern "C" void kernel_launch(void* const* d_in, const int* in_sizes, int n_in,
                              void* d_out, int out_size) {
    const float* x    = (const float*)d_in[0];
    const int*   ei   = (const int*)d_in[1];
    const float* ee   = (const float*)d_in[2];
    const float* Wg   = (const float*)d_in[4];
    const float* bg   = (const float*)d_in[5];
    const float* root = (const float*)d_in[6];
    const float* Wq   = (const float*)d_in[7];
    const float* Wkv  = (const float*)d_in[8];
    const float* Wo   = (const float*)d_in[9];
    const float* bo   = (const float*)d_in[10];
    float* outp = (float*)d_out;

    float *p_h2, *p_ao;
    cudaGetSymbolAddress((void**)&p_h2, g_h2);
    cudaGetSymbolAddress((void**)&p_ao, g_ao);

    const int GEMM_SMEM = GEMM_SMEM_FLOATS * 4;   // 100864 B
    const int ATTN_SMEM = 128 * 1024;
    cudaFuncSetAttribute(scatter_gcn_kernel, cudaFuncAttributeMaxDynamicSharedMemorySize, GEMM_SMEM);
    cudaFuncSetAttribute(qkv_gemm_kernel,    cudaFuncAttributeMaxDynamicSharedMemorySize, GEMM_SMEM);
    cudaFuncSetAttribute(out_gemm_kernel,    cudaFuncAttributeMaxDynamicSharedMemorySize, GEMM_SMEM);
    cudaFuncSetAttribute(attn_kernel,        cudaFuncAttributeMaxDynamicSharedMemorySize, ATTN_SMEM);

    // 0: scatter + GCN gemm (direct W) + wtrans(q,kv,out)
    scatter_gcn_kernel<<<64 + 2560, 256, GEMM_SMEM>>>(ei, x, Wg, bg, Wq, Wkv, Wo);
    // 1: gather -> h2
    gather_kernel<<<TN / 8, 256>>>(ee, root);
    // 2: fused q + kv projections
    qkv_gemm_kernel<<<dim3(TN / 128, 6), 256, GEMM_SMEM>>>(p_h2);
    // 3: attention  (PROFILED SLOT)
    attn_kernel<<<BG * NH, 256, ATTN_SMEM>>>();
    // 4: out = ao @ Wout + b_out  (+ counter reset for next replay)
    out_gemm_kernel<<<dim3(256 + 32, 2), 256, GEMM_SMEM>>>(p_ao, bo, outp);
}